// round 14
// baseline (speedup 1.0000x reference)
#include <cuda_runtime.h>
#include <cuda_fp16.h>
#include <math.h>
#include <stdint.h>

// ---------------- problem constants ----------------
#define BN    48
#define CCH   128
#define NWIN  49
#define NTOK  49
#define MROWS (BN*NWIN*NTOK)   // 115248
#define HID   512
#define QSCALE 0.17677669529663687f

// ---------------- scratch (device globals) ----------------
__device__ __half g_xw [(size_t)MROWS*CCH];
__device__ __half g_ln2[(size_t)MROWS*CCH];
__device__ __half g_big[(size_t)MROWS*HID];
__device__ float  g_x2 [(size_t)MROWS*CCH];
__device__ __half g_wts[196608];
__device__ float  g_qkvb[384];
__device__ float  g_bm [49*4*64*64];
#define WOFF_QKV 0
#define WOFF_PROJ 49152
#define WOFF_FC1  65536
#define WOFF_FC2  131072

// ---------------- asm helpers ----------------
__device__ __forceinline__ uint32_t smem_u32(const void* p) {
    return (uint32_t)__cvta_generic_to_shared(p);
}
__device__ __forceinline__ void cp_async16(uint32_t dst, const void* src, int sz) {
    asm volatile("cp.async.cg.shared.global [%0], [%1], 16, %2;"
                 :: "r"(dst), "l"(src), "r"(sz));
}
__device__ __forceinline__ void ldsm_x4(uint32_t r[4], uint32_t addr) {
    asm volatile("ldmatrix.sync.aligned.m8n8.x4.shared.b16 {%0,%1,%2,%3}, [%4];"
                 : "=r"(r[0]), "=r"(r[1]), "=r"(r[2]), "=r"(r[3]) : "r"(addr));
}
__device__ __forceinline__ void ldsm_x4_t(uint32_t r[4], uint32_t addr) {
    asm volatile("ldmatrix.sync.aligned.m8n8.x4.trans.shared.b16 {%0,%1,%2,%3}, [%4];"
                 : "=r"(r[0]), "=r"(r[1]), "=r"(r[2]), "=r"(r[3]) : "r"(addr));
}
__device__ __forceinline__ void mma_f16f32(float c[4], const uint32_t a[4],
                                           uint32_t b0, uint32_t b1) {
    asm volatile("mma.sync.aligned.m16n8k16.row.col.f32.f16.f16.f32 "
                 "{%0,%1,%2,%3}, {%4,%5,%6,%7}, {%8,%9}, {%0,%1,%2,%3};"
                 : "+f"(c[0]), "+f"(c[1]), "+f"(c[2]), "+f"(c[3])
                 : "r"(a[0]), "r"(a[1]), "r"(a[2]), "r"(a[3]), "r"(b0), "r"(b1));
}
__device__ __forceinline__ void mma_f16h(uint32_t c[2], const uint32_t a[4],
                                         uint32_t b0, uint32_t b1) {
    asm volatile("mma.sync.aligned.m16n8k16.row.col.f16.f16.f16.f16 "
                 "{%0,%1}, {%2,%3,%4,%5}, {%6,%7}, {%0,%1};"
                 : "+r"(c[0]), "+r"(c[1])
                 : "r"(a[0]), "r"(a[1]), "r"(a[2]), "r"(a[3]), "r"(b0), "r"(b1));
}

// ---------------- weight convert (q rows pre-scaled) ----------------
__global__ void cvt_weights(const float* __restrict__ qkv_w, const float* __restrict__ proj_w,
                            const float* __restrict__ fc1_w, const float* __restrict__ fc2_w,
                            const float* __restrict__ qkv_b) {
    int i = blockIdx.x * 256 + threadIdx.x;
    if (i < 49152) {
        float v = qkv_w[i];
        if (i < 16384) v *= QSCALE;
        g_wts[WOFF_QKV + i] = __float2half_rn(v);
    }
    if (i < 16384)       g_wts[WOFF_PROJ + i] = __float2half_rn(proj_w[i]);
    if (i < 65536) {     g_wts[WOFF_FC1  + i] = __float2half_rn(fc1_w[i]);
                         g_wts[WOFF_FC2  + i] = __float2half_rn(fc2_w[i]); }
    if (i < 384)         g_qkvb[i] = qkv_b[i] * (i < 128 ? QSCALE : 1.f);
}

// ---------------- bias+mask table ----------------
__device__ __forceinline__ int regn(int wq, int iq) {
    return (wq < 6) ? 0 : ((iq < 4) ? 1 : 2);
}
__global__ void build_bm(const float* __restrict__ rpb) {
    int w = blockIdx.x, h = blockIdx.y;
    int wh = w / 7, ww = w % 7;
    for (int e = threadIdx.x; e < 64 * 64; e += 256) {
        int n = e >> 6, m = e & 63;
        float v;
        if (n < 49 && m < 49) {
            int i1 = n / 7, j1 = n % 7, i2 = m / 7, j2 = m % 7;
            v = rpb[((i1 - i2 + 6) * 13 + (j1 - j2 + 6)) * 4 + h];
            int mwW = regn(wh, i2) * 3 + regn(ww, j2);
            int mwN = regn(i1, i2) * 3 + regn(j1, j2);
            if (mwW != mwN) v -= 100.f;
        } else {
            v = -1e9f;
        }
        g_bm[((size_t)(w * 4 + h) * 64 + n) * 64 + m] = v;
    }
}

// ---------------- LN1 + shift + window gather ----------------
__global__ void ln1_gather_kernel(const float* __restrict__ x,
                                  const float* __restrict__ w,
                                  const float* __restrict__ b) {
    int t = blockIdx.x, c = threadIdx.x;
    int bw = t / NTOK, n = t - bw * NTOK;
    int bb = bw / NWIN, wi = bw - bb * NWIN;
    int R  = (wi / 7) * 7 + n / 7;
    int Cl = (wi % 7) * 7 + n % 7;
    int sr = R + 3;  if (sr >= 49) sr -= 49;
    int sc = Cl + 3; if (sc >= 49) sc -= 49;
    float v = x[((size_t)bb * 2401 + sr * 49 + sc) * CCH + c];
    float s = v, s2 = v * v;
    #pragma unroll
    for (int o = 16; o > 0; o >>= 1) {
        s  += __shfl_xor_sync(0xffffffffu, s,  o);
        s2 += __shfl_xor_sync(0xffffffffu, s2, o);
    }
    __shared__ float red[8];
    int wid = c >> 5, lane = c & 31;
    if (lane == 0) { red[wid] = s; red[4 + wid] = s2; }
    __syncthreads();
    float ts  = red[0] + red[1] + red[2] + red[3];
    float ts2 = red[4] + red[5] + red[6] + red[7];
    float mean = ts * (1.f / 128.f);
    float var  = ts2 * (1.f / 128.f) - mean * mean;
    float rstd = rsqrtf(var + 1e-5f);
    g_xw[(size_t)t * CCH + c] = __float2half_rn((v - mean) * rstd * w[c] + b[c]);
}

// ---------------- tensor-core attention (unchanged, passing) ----------------
__global__ void __launch_bounds__(128) attn_kernel() {
    int bw = blockIdx.x, h = blockIdx.y;
    int w  = bw % NWIN;
    int tid = threadIdx.x, lane = tid & 31, warp = tid >> 5;

    __shared__ __align__(16) uint8_t sQ[64 * 64];
    __shared__ __align__(16) uint8_t sK[64 * 64];
    __shared__ __align__(16) uint8_t sV[64 * 64];
    __shared__ __align__(16) uint8_t sP[64 * 128];

    uint32_t qb = smem_u32(sQ), kb = smem_u32(sK);
    uint32_t vb = smem_u32(sV), pb = smem_u32(sP);

    const __half* base = g_big + (size_t)bw * NTOK * 384;
    for (int id = tid; id < 768; id += 128) {
        int op = id >> 8;
        int r  = (id >> 2) & 63;
        int c  = id & 3;
        uint32_t sb = (op == 0) ? qb : (op == 1) ? kb : vb;
        uint32_t dst = sb + r * 64 + ((c ^ ((r >> 1) & 3)) << 4);
        const __half* src = base + (r < 49 ? r : 0) * 384 + op * 128 + h * 32 + c * 8;
        cp_async16(dst, src, r < 49 ? 16 : 0);
    }
    asm volatile("cp.async.commit_group;");
    asm volatile("cp.async.wait_group 0;");
    __syncthreads();

    int g = lane >> 2, tg = lane & 3;
    int m0 = warp * 16;

    float acc[8][4];
    #pragma unroll
    for (int i = 0; i < 8; i++)
        #pragma unroll
        for (int j = 0; j < 4; j++) acc[i][j] = 0.f;

    #pragma unroll
    for (int ks = 0; ks < 2; ks++) {
        uint32_t aF[4];
        {
            int r = m0 + (lane & 15);
            int c = 2 * ks + (lane >> 4);
            ldsm_x4(aF, qb + r * 64 + ((c ^ ((r >> 1) & 3)) << 4));
        }
        #pragma unroll
        for (int nfp = 0; nfp < 4; nfp++) {
            uint32_t bF[4];
            int r = nfp * 16 + (lane & 7) + ((lane >> 4) & 1) * 8;
            int c = 2 * ks + ((lane >> 3) & 1);
            ldsm_x4(bF, kb + r * 64 + ((c ^ ((r >> 1) & 3)) << 4));
            mma_f16f32(acc[nfp * 2],     aF, bF[0], bF[1]);
            mma_f16f32(acc[nfp * 2 + 1], aF, bF[2], bF[3]);
        }
    }

    const float* bm = g_bm + (size_t)(w * 4 + h) * 64 * 64;
    #pragma unroll
    for (int hh = 0; hh < 2; hh++) {
        int n = m0 + g + hh * 8;
        const float* bmr = bm + n * 64;
        float vals[16];
        #pragma unroll
        for (int nf = 0; nf < 8; nf++) {
            float2 bv = *(const float2*)(bmr + nf * 8 + tg * 2);
            vals[nf * 2]     = acc[nf][hh * 2]     + bv.x;
            vals[nf * 2 + 1] = acc[nf][hh * 2 + 1] + bv.y;
        }
        float mx = vals[0];
        #pragma unroll
        for (int i = 1; i < 16; i++) mx = fmaxf(mx, vals[i]);
        mx = fmaxf(mx, __shfl_xor_sync(0xffffffffu, mx, 1));
        mx = fmaxf(mx, __shfl_xor_sync(0xffffffffu, mx, 2));
        float sum = 0.f;
        #pragma unroll
        for (int i = 0; i < 16; i++) { vals[i] = __expf(vals[i] - mx); sum += vals[i]; }
        sum += __shfl_xor_sync(0xffffffffu, sum, 1);
        sum += __shfl_xor_sync(0xffffffffu, sum, 2);
        float inv = 1.f / sum;
        #pragma unroll
        for (int nf = 0; nf < 8; nf++) {
            __half2 p;
            p.x = __float2half_rn(vals[nf * 2] * inv);
            p.y = __float2half_rn(vals[nf * 2 + 1] * inv);
            *(uint32_t*)(sP + n * 128 + ((nf ^ (n & 7)) << 4) + tg * 4) = *(uint32_t*)&p;
        }
    }
    __syncwarp();

    float acc2[4][4];
    #pragma unroll
    for (int i = 0; i < 4; i++)
        #pragma unroll
        for (int j = 0; j < 4; j++) acc2[i][j] = 0.f;

    #pragma unroll
    for (int ks = 0; ks < 4; ks++) {
        uint32_t aF[4];
        {
            int r = m0 + (lane & 15);
            int c = 2 * ks + (lane >> 4);
            ldsm_x4(aF, pb + r * 128 + ((c ^ (r & 7)) << 4));
        }
        #pragma unroll
        for (int nfp = 0; nfp < 2; nfp++) {
            uint32_t bF[4];
            int rv = ks * 16 + (lane & 7) + ((lane >> 3) & 1) * 8;
            int cv = nfp * 2 + (lane >> 4);
            ldsm_x4_t(bF, vb + rv * 64 + ((cv ^ ((rv >> 1) & 3)) << 4));
            mma_f16f32(acc2[nfp * 2],     aF, bF[0], bF[1]);
            mma_f16f32(acc2[nfp * 2 + 1], aF, bF[2], bF[3]);
        }
    }

    #pragma unroll
    for (int hh = 0; hh < 2; hh++) {
        int n = m0 + g + hh * 8;
        if (n < 49) {
            __half* dst = g_xw + ((size_t)bw * NTOK + n) * CCH + h * 32;
            #pragma unroll
            for (int nf = 0; nf < 4; nf++) {
                __half2 o;
                o.x = __float2half_rn(acc2[nf][hh * 2]);
                o.y = __float2half_rn(acc2[nf][hh * 2 + 1]);
                *(uint32_t*)(dst + nf * 8 + tg * 2) = *(uint32_t*)&o;
            }
        }
    }
}

// ---------------- 256x128 CTA GEMM, 8 warps of 64x64, f16 accum, dynamic smem ----
// Stage: A 256x32 (16KB) + W 128x32 (8KB) = 24KB; 3 stages = 72KB.
// EPI 0: qkv  EPI 1: proj+scatter+residual+fused LN2  EPI 2: fc1+GELU  EPI 3: fc2+res
#define BK 32
#define STAGES 3
#define STG_BYTES 24576
#define A_BYTES 16384

template <int EPI, int K>
__global__ void __launch_bounds__(256, 2)
mma_gemm(const __half* __restrict__ Wb, const float* __restrict__ bias,
         const float* __restrict__ aux, float* __restrict__ extC,
         const float* __restrict__ n2w, const float* __restrict__ n2b, int M) {
    extern __shared__ __align__(16) uint8_t smem[];
    __shared__ float sred[256 * 2 * 2];

    const __half* A = (EPI == 3) ? g_big : ((EPI == 2) ? g_ln2 : g_xw);
    constexpr int nkt = K / BK;

    int tid = threadIdx.x, lane = tid & 31, warp = tid >> 5;
    int row0 = blockIdx.x * 256, col0 = blockIdx.y * 128;
    int wm = warp & 3, wn = warp >> 2;   // 4 x 2 warp grid, 64x64 each
    int g = lane >> 2, tg = lane & 3;

    uint32_t accH[4][8][2];
    #pragma unroll
    for (int i = 0; i < 4; i++)
        #pragma unroll
        for (int j = 0; j < 8; j++) { accH[i][j][0] = 0u; accH[i][j][1] = 0u; }

    uint32_t sbase = smem_u32(smem);

    // loader addresses (hoisted)
    const int ldr = tid >> 2, ldc = tid & 3;   // ldr 0..63
    uint32_t aoffL[4]; const __half* AbaseL[4]; int okA[4];
    uint32_t boffL[2]; const __half* WbaseL[2];
    #pragma unroll
    for (int h = 0; h < 4; h++) {
        int r = ldr + h * 64;
        aoffL[h] = (uint32_t)(r * 64 + ((ldc ^ ((r >> 1) & 3)) << 4));
        AbaseL[h] = A + (size_t)(row0 + r) * K + ldc * 8;
        okA[h] = (row0 + r) < M ? 16 : 0;
    }
    #pragma unroll
    for (int h = 0; h < 2; h++) {
        int r = ldr + h * 64;
        boffL[h] = (uint32_t)(r * 64 + ((ldc ^ ((r >> 1) & 3)) << 4));
        WbaseL[h] = Wb + (size_t)(col0 + r) * K + ldc * 8;
    }

    auto load_tile = [&](int kt, int st) {
        uint32_t sa = sbase + st * STG_BYTES;
        uint32_t sb = sa + A_BYTES;
        #pragma unroll
        for (int h = 0; h < 4; h++) cp_async16(sa + aoffL[h], AbaseL[h] + kt * BK, okA[h]);
        #pragma unroll
        for (int h = 0; h < 2; h++) cp_async16(sb + boffL[h], WbaseL[h] + kt * BK, 16);
        asm volatile("cp.async.commit_group;");
    };

    // fragment addresses (hoisted)
    uint32_t aoff[2][4], boff[2][4];
    #pragma unroll
    for (int ks = 0; ks < 2; ks++) {
        #pragma unroll
        for (int mf = 0; mf < 4; mf++) {
            int r = wm * 64 + mf * 16 + (lane & 15);
            int c = 2 * ks + (lane >> 4);
            aoff[ks][mf] = (uint32_t)(r * 64 + ((c ^ ((r >> 1) & 3)) << 4));
        }
        #pragma unroll
        for (int nfp = 0; nfp < 4; nfp++) {
            int r = wn * 64 + nfp * 16 + (lane & 7) + ((lane >> 4) & 1) * 8;
            int c = 2 * ks + ((lane >> 3) & 1);
            boff[ks][nfp] = (uint32_t)(r * 64 + ((c ^ ((r >> 1) & 3)) << 4));
        }
    }

    load_tile(0, 0);
    load_tile(1, 1);

    #pragma unroll
    for (int kt = 0; kt < nkt; kt++) {
        if (kt < nkt - 1) asm volatile("cp.async.wait_group 1;");
        else              asm volatile("cp.async.wait_group 0;");
        __syncthreads();
        if (kt + 2 < nkt) load_tile(kt + 2, (kt + 2) % STAGES);

        uint32_t sa = sbase + (kt % STAGES) * STG_BYTES;
        uint32_t sb = sa + A_BYTES;
        #pragma unroll
        for (int ks = 0; ks < 2; ks++) {
            uint32_t bF[4][4];
            #pragma unroll
            for (int nfp = 0; nfp < 4; nfp++) ldsm_x4(bF[nfp], sb + boff[ks][nfp]);
            #pragma unroll
            for (int mf = 0; mf < 4; mf++) {
                uint32_t aF[4];
                ldsm_x4(aF, sa + aoff[ks][mf]);
                #pragma unroll
                for (int nf = 0; nf < 8; nf++)
                    mma_f16h(accH[mf][nf], aF,
                             bF[nf >> 1][(nf & 1) * 2], bF[nf >> 1][(nf & 1) * 2 + 1]);
            }
        }
    }

    auto scatter_of = [](int r) -> size_t {
        int bw = r / 49, tok = r - bw * 49;
        int bb = bw / 49, wi = bw - bb * 49;
        int R  = (wi / 7) * 7 + tok / 7;
        int Cl = (wi % 7) * 7 + tok % 7;
        int rr = R + 3;  if (rr >= 49) rr -= 49;
        int cc = Cl + 3; if (cc >= 49) cc -= 49;
        return ((size_t)bb * 2401 + rr * 49 + cc) * 128;
    };

    if (EPI == 1) {
        #pragma unroll
        for (int mf = 0; mf < 4; mf++) {
            #pragma unroll
            for (int hh = 0; hh < 2; hh++) {
                int rl = wm * 64 + mf * 16 + g + hh * 8;
                int r = row0 + rl;
                bool ok = r < M;
                size_t dest = scatter_of(ok ? r : (M - 1));
                float s = 0.f, s2 = 0.f;
                #pragma unroll
                for (int nf = 0; nf < 8; nf++) {
                    int n = wn * 64 + nf * 8 + tg * 2;
                    __half2 hv = *reinterpret_cast<__half2*>(&accH[mf][nf][hh]);
                    float2 a2 = *reinterpret_cast<const float2*>(aux + dest + n);
                    float2 b2 = *reinterpret_cast<const float2*>(bias + n);
                    float2 v;
                    v.x = __low2float(hv)  + b2.x + a2.x;
                    v.y = __high2float(hv) + b2.y + a2.y;
                    if (ok) *reinterpret_cast<float2*>(g_x2 + dest + n) = v;
                    s  += v.x + v.y;
                    s2 += v.x * v.x + v.y * v.y;
                }
                s  += __shfl_xor_sync(0xffffffffu, s,  1);
                s2 += __shfl_xor_sync(0xffffffffu, s2, 1);
                s  += __shfl_xor_sync(0xffffffffu, s,  2);
                s2 += __shfl_xor_sync(0xffffffffu, s2, 2);
                if (tg == 0) {
                    sred[(rl * 2 + wn) * 2]     = s;
                    sred[(rl * 2 + wn) * 2 + 1] = s2;
                }
            }
        }
        __syncthreads();
        #pragma unroll
        for (int mf = 0; mf < 4; mf++) {
            #pragma unroll
            for (int hh = 0; hh < 2; hh++) {
                int rl = wm * 64 + mf * 16 + g + hh * 8;
                int r = row0 + rl;
                bool ok = r < M;
                size_t dest = scatter_of(ok ? r : (M - 1));
                float ts  = sred[(rl * 2) * 2]     + sred[(rl * 2 + 1) * 2];
                float ts2 = sred[(rl * 2) * 2 + 1] + sred[(rl * 2 + 1) * 2 + 1];
                float mean = ts * (1.f / 128.f);
                float var  = ts2 * (1.f / 128.f) - mean * mean;
                float rstd = rsqrtf(var + 1e-5f);
                if (ok) {
                    #pragma unroll
                    for (int nf = 0; nf < 8; nf++) {
                        int n = wn * 64 + nf * 8 + tg * 2;
                        float2 v = *reinterpret_cast<const float2*>(g_x2 + dest + n);
                        float2 w2 = *reinterpret_cast<const float2*>(n2w + n);
                        float2 c2 = *reinterpret_cast<const float2*>(n2b + n);
                        __half2 o;
                        o.x = __float2half_rn((v.x - mean) * rstd * w2.x + c2.x);
                        o.y = __float2half_rn((v.y - mean) * rstd * w2.y + c2.y);
                        *reinterpret_cast<uint32_t*>(g_ln2 + dest + n) = *(uint32_t*)&o;
                    }
                }
            }
        }
    } else {
        #pragma unroll
        for (int mf = 0; mf < 4; mf++) {
            #pragma unroll
            for (int hh = 0; hh < 2; hh++) {
                int r = row0 + wm * 64 + mf * 16 + g + hh * 8;
                if (r >= M) continue;
                #pragma unroll
                for (int nf = 0; nf < 8; nf++) {
                    int n = col0 + wn * 64 + nf * 8 + tg * 2;
                    __half2 hv = *reinterpret_cast<__half2*>(&accH[mf][nf][hh]);
                    float2 b2 = *reinterpret_cast<const float2*>(bias + n);
                    float vx = __low2float(hv)  + b2.x;
                    float vy = __high2float(hv) + b2.y;
                    if (EPI == 0) {
                        __half2 o; o.x = __float2half_rn(vx); o.y = __float2half_rn(vy);
                        *reinterpret_cast<uint32_t*>(g_big + (size_t)r * 384 + n) = *(uint32_t*)&o;
                    } else if (EPI == 2) {
                        vx = 0.5f * vx * (1.f + erff(vx * 0.70710678118654752f));
                        vy = 0.5f * vy * (1.f + erff(vy * 0.70710678118654752f));
                        __half2 o; o.x = __float2half_rn(vx); o.y = __float2half_rn(vy);
                        *reinterpret_cast<uint32_t*>(g_big + (size_t)r * 512 + n) = *(uint32_t*)&o;
                    } else {
                        float2 x2v = *reinterpret_cast<const float2*>(g_x2 + (size_t)r * 128 + n);
                        float2 o; o.x = vx + x2v.x; o.y = vy + x2v.y;
                        *reinterpret_cast<float2*>(extC + (size_t)r * 128 + n) = o;
                    }
                }
            }
        }
    }
}

// ---------------- launch ----------------
extern "C" void kernel_launch(void* const* d_in, const int* in_sizes, int n_in,
                              void* d_out, int out_size) {
    const float* x      = (const float*)d_in[0];
    const float* n1w    = (const float*)d_in[1];
    const float* n1b    = (const float*)d_in[2];
    const float* qkv_w  = (const float*)d_in[3];
    const float* qkv_b  = (const float*)d_in[4];
    const float* proj_w = (const float*)d_in[5];
    const float* proj_b = (const float*)d_in[6];
    const float* rpb    = (const float*)d_in[7];
    const float* n2w    = (const float*)d_in[8];
    const float* n2b    = (const float*)d_in[9];
    const float* fc1_w  = (const float*)d_in[10];
    const float* fc1_b  = (const float*)d_in[11];
    const float* fc2_w  = (const float*)d_in[12];
    const float* fc2_b  = (const float*)d_in[13];
    float* out = (float*)d_out;

    const int M = MROWS;
    const int gm = (M + 255) / 256;   // 451
    const int SMEM_SZ = STAGES * STG_BYTES;   // 72KB

    cudaFuncSetAttribute(mma_gemm<0,128>, cudaFuncAttributeMaxDynamicSharedMemorySize, SMEM_SZ);
    cudaFuncSetAttribute(mma_gemm<1,128>, cudaFuncAttributeMaxDynamicSharedMemorySize, SMEM_SZ);
    cudaFuncSetAttribute(mma_gemm<2,128>, cudaFuncAttributeMaxDynamicSharedMemorySize, SMEM_SZ);
    cudaFuncSetAttribute(mma_gemm<3,512>, cudaFuncAttributeMaxDynamicSharedMemorySize, SMEM_SZ);

    cvt_weights<<<256, 256>>>(qkv_w, proj_w, fc1_w, fc2_w, qkv_b);
    build_bm<<<dim3(49, 4), 256>>>(rpb);
    ln1_gather_kernel<<<M, 128>>>(x, n1w, n1b);

    __half* wbase;
    float* qb;
    cudaGetSymbolAddress((void**)&wbase, g_wts);
    cudaGetSymbolAddress((void**)&qb, g_qkvb);

    mma_gemm<0,128><<<dim3(gm, 3), 256, SMEM_SZ>>>(wbase + WOFF_QKV, qb, nullptr, nullptr, nullptr, nullptr, M);
    attn_kernel<<<dim3(BN * NWIN, 4), 128>>>();
    mma_gemm<1,128><<<dim3(gm, 1), 256, SMEM_SZ>>>(wbase + WOFF_PROJ, proj_b, x, nullptr, n2w, n2b, M);
    mma_gemm<2,128><<<dim3(gm, 4), 256, SMEM_SZ>>>(wbase + WOFF_FC1, fc1_b, nullptr, nullptr, nullptr, nullptr, M);
    mma_gemm<3,512><<<dim3(gm, 1), 256, SMEM_SZ>>>(wbase + WOFF_FC2, fc2_b, nullptr, out, nullptr, nullptr, M);
}

// round 15
// speedup vs baseline: 1.4512x; 1.4512x over previous
#include <cuda_runtime.h>
#include <cuda_fp16.h>
#include <math.h>
#include <stdint.h>

// ---------------- problem constants ----------------
#define BN    48
#define CCH   128
#define NWIN  49
#define NTOK  49
#define MROWS (BN*NWIN*NTOK)   // 115248
#define HID   512
#define QSCALE 0.17677669529663687f

// ---------------- scratch (device globals) ----------------
__device__ __half g_xw [(size_t)MROWS*CCH];   // LN1 out -> attn out (window order)
__device__ __half g_ln2[(size_t)MROWS*CCH];   // LN2 out (x layout) -> fc1 input
__device__ __half g_big[(size_t)MROWS*HID];   // qkv (stride 384) then hidden (stride 512)
__device__ float  g_x2 [(size_t)MROWS*CCH];   // fp32 residual (x layout)
__device__ __half g_wts[196608];
__device__ float  g_qkvb[384];
__device__ __half g_bm [49*4*64*64];          // bias+mask table (fp16)
#define WOFF_QKV 0
#define WOFF_PROJ 49152
#define WOFF_FC1  65536
#define WOFF_FC2  131072

// ---------------- asm helpers ----------------
__device__ __forceinline__ uint32_t smem_u32(const void* p) {
    return (uint32_t)__cvta_generic_to_shared(p);
}
__device__ __forceinline__ void cp_async16(uint32_t dst, const void* src, int sz) {
    asm volatile("cp.async.cg.shared.global [%0], [%1], 16, %2;"
                 :: "r"(dst), "l"(src), "r"(sz));
}
__device__ __forceinline__ void ldsm_x4(uint32_t r[4], uint32_t addr) {
    asm volatile("ldmatrix.sync.aligned.m8n8.x4.shared.b16 {%0,%1,%2,%3}, [%4];"
                 : "=r"(r[0]), "=r"(r[1]), "=r"(r[2]), "=r"(r[3]) : "r"(addr));
}
__device__ __forceinline__ void ldsm_x4_t(uint32_t r[4], uint32_t addr) {
    asm volatile("ldmatrix.sync.aligned.m8n8.x4.trans.shared.b16 {%0,%1,%2,%3}, [%4];"
                 : "=r"(r[0]), "=r"(r[1]), "=r"(r[2]), "=r"(r[3]) : "r"(addr));
}
__device__ __forceinline__ void mma_f16f32(float c[4], const uint32_t a[4],
                                           uint32_t b0, uint32_t b1) {
    asm volatile("mma.sync.aligned.m16n8k16.row.col.f32.f16.f16.f32 "
                 "{%0,%1,%2,%3}, {%4,%5,%6,%7}, {%8,%9}, {%0,%1,%2,%3};"
                 : "+f"(c[0]), "+f"(c[1]), "+f"(c[2]), "+f"(c[3])
                 : "r"(a[0]), "r"(a[1]), "r"(a[2]), "r"(a[3]), "r"(b0), "r"(b1));
}
__device__ __forceinline__ void mma_f16h(uint32_t c[2], const uint32_t a[4],
                                         uint32_t b0, uint32_t b1) {
    asm volatile("mma.sync.aligned.m16n8k16.row.col.f16.f16.f16.f16 "
                 "{%0,%1}, {%2,%3,%4,%5}, {%6,%7}, {%0,%1};"
                 : "+r"(c[0]), "+r"(c[1])
                 : "r"(a[0]), "r"(a[1]), "r"(a[2]), "r"(a[3]), "r"(b0), "r"(b1));
}

// ---------------- weight convert (q rows pre-scaled) ----------------
__global__ void cvt_weights(const float* __restrict__ qkv_w, const float* __restrict__ proj_w,
                            const float* __restrict__ fc1_w, const float* __restrict__ fc2_w,
                            const float* __restrict__ qkv_b) {
    int i = blockIdx.x * 256 + threadIdx.x;
    if (i < 49152) {
        float v = qkv_w[i];
        if (i < 16384) v *= QSCALE;
        g_wts[WOFF_QKV + i] = __float2half_rn(v);
    }
    if (i < 16384)       g_wts[WOFF_PROJ + i] = __float2half_rn(proj_w[i]);
    if (i < 65536) {     g_wts[WOFF_FC1  + i] = __float2half_rn(fc1_w[i]);
                         g_wts[WOFF_FC2  + i] = __float2half_rn(fc2_w[i]); }
    if (i < 384)         g_qkvb[i] = qkv_b[i] * (i < 128 ? QSCALE : 1.f);
}

// ---------------- bias+mask table (fp16) ----------------
__device__ __forceinline__ int regn(int wq, int iq) {
    return (wq < 6) ? 0 : ((iq < 4) ? 1 : 2);
}
__global__ void build_bm(const float* __restrict__ rpb) {
    int w = blockIdx.x, h = blockIdx.y;
    int wh = w / 7, ww = w % 7;
    for (int e = threadIdx.x; e < 64 * 64; e += 256) {
        int n = e >> 6, m = e & 63;
        float v;
        if (n < 49 && m < 49) {
            int i1 = n / 7, j1 = n % 7, i2 = m / 7, j2 = m % 7;
            v = rpb[((i1 - i2 + 6) * 13 + (j1 - j2 + 6)) * 4 + h];
            int mwW = regn(wh, i2) * 3 + regn(ww, j2);
            int mwN = regn(i1, i2) * 3 + regn(j1, j2);
            if (mwW != mwN) v -= 100.f;
        } else {
            v = -30000.f;    // masked; exp -> 0, representable in half
        }
        g_bm[((size_t)(w * 4 + h) * 64 + n) * 64 + m] = __float2half_rn(v);
    }
}

// ---------------- LN1 + shift + window gather: warp-per-row, float4 loads ------
__global__ void __launch_bounds__(256) ln1_gather_kernel(const float* __restrict__ x,
                                                         const float* __restrict__ w,
                                                         const float* __restrict__ b) {
    int t = blockIdx.x * 8 + (threadIdx.x >> 5);
    int lane = threadIdx.x & 31;
    if (t >= MROWS) return;
    int bw = t / NTOK, n = t - bw * NTOK;
    int bb = bw / NWIN, wi = bw - bb * NWIN;
    int R  = (wi / 7) * 7 + n / 7;
    int Cl = (wi % 7) * 7 + n % 7;
    int sr = R + 3;  if (sr >= 49) sr -= 49;
    int sc = Cl + 3; if (sc >= 49) sc -= 49;
    const float* src = x + ((size_t)bb * 2401 + sr * 49 + sc) * CCH;
    float4 v4 = *reinterpret_cast<const float4*>(src + lane * 4);
    float s  = v4.x + v4.y + v4.z + v4.w;
    float s2 = v4.x * v4.x + v4.y * v4.y + v4.z * v4.z + v4.w * v4.w;
    #pragma unroll
    for (int o = 16; o > 0; o >>= 1) {
        s  += __shfl_xor_sync(0xffffffffu, s,  o);
        s2 += __shfl_xor_sync(0xffffffffu, s2, o);
    }
    float mean = s * (1.f / 128.f);
    float var  = s2 * (1.f / 128.f) - mean * mean;
    float rstd = rsqrtf(var + 1e-5f);
    float4 w4 = *reinterpret_cast<const float4*>(w + lane * 4);
    float4 b4 = *reinterpret_cast<const float4*>(b + lane * 4);
    __half2 o0, o1;
    o0.x = __float2half_rn((v4.x - mean) * rstd * w4.x + b4.x);
    o0.y = __float2half_rn((v4.y - mean) * rstd * w4.y + b4.y);
    o1.x = __float2half_rn((v4.z - mean) * rstd * w4.z + b4.z);
    o1.y = __float2half_rn((v4.w - mean) * rstd * w4.w + b4.w);
    uint2 pk = make_uint2(*(uint32_t*)&o0, *(uint32_t*)&o1);
    *reinterpret_cast<uint2*>(g_xw + (size_t)t * CCH + lane * 4) = pk;
}

// ---------------- tensor-core attention (f16 bias table) ----------------
__global__ void __launch_bounds__(128) attn_kernel() {
    int bw = blockIdx.x, h = blockIdx.y;
    int w  = bw % NWIN;
    int tid = threadIdx.x, lane = tid & 31, warp = tid >> 5;

    __shared__ __align__(16) uint8_t sQ[64 * 64];
    __shared__ __align__(16) uint8_t sK[64 * 64];
    __shared__ __align__(16) uint8_t sV[64 * 64];
    __shared__ __align__(16) uint8_t sP[64 * 128];

    uint32_t qb = smem_u32(sQ), kb = smem_u32(sK);
    uint32_t vb = smem_u32(sV), pb = smem_u32(sP);

    const __half* base = g_big + (size_t)bw * NTOK * 384;
    for (int id = tid; id < 768; id += 128) {
        int op = id >> 8;
        int r  = (id >> 2) & 63;
        int c  = id & 3;
        uint32_t sb = (op == 0) ? qb : (op == 1) ? kb : vb;
        uint32_t dst = sb + r * 64 + ((c ^ ((r >> 1) & 3)) << 4);
        const __half* src = base + (r < 49 ? r : 0) * 384 + op * 128 + h * 32 + c * 8;
        cp_async16(dst, src, r < 49 ? 16 : 0);
    }
    asm volatile("cp.async.commit_group;");
    asm volatile("cp.async.wait_group 0;");
    __syncthreads();

    int g = lane >> 2, tg = lane & 3;
    int m0 = warp * 16;

    float acc[8][4];
    #pragma unroll
    for (int i = 0; i < 8; i++)
        #pragma unroll
        for (int j = 0; j < 4; j++) acc[i][j] = 0.f;

    #pragma unroll
    for (int ks = 0; ks < 2; ks++) {
        uint32_t aF[4];
        {
            int r = m0 + (lane & 15);
            int c = 2 * ks + (lane >> 4);
            ldsm_x4(aF, qb + r * 64 + ((c ^ ((r >> 1) & 3)) << 4));
        }
        #pragma unroll
        for (int nfp = 0; nfp < 4; nfp++) {
            uint32_t bF[4];
            int r = nfp * 16 + (lane & 7) + ((lane >> 4) & 1) * 8;
            int c = 2 * ks + ((lane >> 3) & 1);
            ldsm_x4(bF, kb + r * 64 + ((c ^ ((r >> 1) & 3)) << 4));
            mma_f16f32(acc[nfp * 2],     aF, bF[0], bF[1]);
            mma_f16f32(acc[nfp * 2 + 1], aF, bF[2], bF[3]);
        }
    }

    const __half* bm = g_bm + (size_t)(w * 4 + h) * 64 * 64;
    #pragma unroll
    for (int hh = 0; hh < 2; hh++) {
        int n = m0 + g + hh * 8;
        const __half* bmr = bm + n * 64;
        float vals[16];
        #pragma unroll
        for (int nf = 0; nf < 8; nf++) {
            __half2 bh = *(const __half2*)(bmr + nf * 8 + tg * 2);
            float2 bv = __half22float2(bh);
            vals[nf * 2]     = acc[nf][hh * 2]     + bv.x;
            vals[nf * 2 + 1] = acc[nf][hh * 2 + 1] + bv.y;
        }
        float mx = vals[0];
        #pragma unroll
        for (int i = 1; i < 16; i++) mx = fmaxf(mx, vals[i]);
        mx = fmaxf(mx, __shfl_xor_sync(0xffffffffu, mx, 1));
        mx = fmaxf(mx, __shfl_xor_sync(0xffffffffu, mx, 2));
        float sum = 0.f;
        #pragma unroll
        for (int i = 0; i < 16; i++) { vals[i] = __expf(vals[i] - mx); sum += vals[i]; }
        sum += __shfl_xor_sync(0xffffffffu, sum, 1);
        sum += __shfl_xor_sync(0xffffffffu, sum, 2);
        float inv = 1.f / sum;
        #pragma unroll
        for (int nf = 0; nf < 8; nf++) {
            __half2 p;
            p.x = __float2half_rn(vals[nf * 2] * inv);
            p.y = __float2half_rn(vals[nf * 2 + 1] * inv);
            *(uint32_t*)(sP + n * 128 + ((nf ^ (n & 7)) << 4) + tg * 4) = *(uint32_t*)&p;
        }
    }
    __syncwarp();

    float acc2[4][4];
    #pragma unroll
    for (int i = 0; i < 4; i++)
        #pragma unroll
        for (int j = 0; j < 4; j++) acc2[i][j] = 0.f;

    #pragma unroll
    for (int ks = 0; ks < 4; ks++) {
        uint32_t aF[4];
        {
            int r = m0 + (lane & 15);
            int c = 2 * ks + (lane >> 4);
            ldsm_x4(aF, pb + r * 128 + ((c ^ (r & 7)) << 4));
        }
        #pragma unroll
        for (int nfp = 0; nfp < 2; nfp++) {
            uint32_t bF[4];
            int rv = ks * 16 + (lane & 7) + ((lane >> 3) & 1) * 8;
            int cv = nfp * 2 + (lane >> 4);
            ldsm_x4_t(bF, vb + rv * 64 + ((cv ^ ((rv >> 1) & 3)) << 4));
            mma_f16f32(acc2[nfp * 2],     aF, bF[0], bF[1]);
            mma_f16f32(acc2[nfp * 2 + 1], aF, bF[2], bF[3]);
        }
    }

    #pragma unroll
    for (int hh = 0; hh < 2; hh++) {
        int n = m0 + g + hh * 8;
        if (n < 49) {
            __half* dst = g_xw + ((size_t)bw * NTOK + n) * CCH + h * 32;
            #pragma unroll
            for (int nf = 0; nf < 4; nf++) {
                __half2 o;
                o.x = __float2half_rn(acc2[nf][hh * 2]);
                o.y = __float2half_rn(acc2[nf][hh * 2 + 1]);
                *(uint32_t*)(dst + nf * 8 + tg * 2) = *(uint32_t*)&o;
            }
        }
    }
}

// ---------------- f16-accum GEMM (R13 config: 128x128 CTA, 64x32 warp tile) -----
// EPI 0: qkv  EPI 1: proj+scatter+residual+fused LN2  EPI 2: fc1+GELU  EPI 3: fc2+res
#define BK 32
#define STAGES 3
#define TILE_B 8192

template <int EPI, int K>
__global__ void __launch_bounds__(256, 2)
mma_gemm(const __half* __restrict__ Wb, const float* __restrict__ bias,
         const float* __restrict__ aux, float* __restrict__ extC,
         const float* __restrict__ n2w, const float* __restrict__ n2b, int M) {
    __shared__ __align__(16) uint8_t smem[STAGES * 2 * TILE_B];
    __shared__ float sred[128 * 4 * 2];

    const __half* A = (EPI == 3) ? g_big : ((EPI == 2) ? g_ln2 : g_xw);
    constexpr int nkt = K / BK;

    int tid = threadIdx.x, lane = tid & 31, warp = tid >> 5;
    int row0 = blockIdx.x * 128, col0 = blockIdx.y * 128;
    int wm = warp & 1, wn = warp >> 1;
    int g = lane >> 2, tg = lane & 3;

    uint32_t accH[4][4][2];
    #pragma unroll
    for (int i = 0; i < 4; i++)
        #pragma unroll
        for (int j = 0; j < 4; j++) { accH[i][j][0] = 0u; accH[i][j][1] = 0u; }

    uint32_t sbase = smem_u32(smem);

    const int ldr = tid >> 2, ldc = tid & 3;
    const uint32_t ldoff0 = (uint32_t)(ldr * 64 + ((ldc ^ ((ldr >> 1) & 3)) << 4));
    const int ldr1 = ldr + 64;
    const uint32_t ldoff1 = (uint32_t)(ldr1 * 64 + ((ldc ^ ((ldr1 >> 1) & 3)) << 4));
    const __half* Abase  = A  + (size_t)(row0 + ldr)  * K + ldc * 8;
    const __half* Abase1 = A  + (size_t)(row0 + ldr1) * K + ldc * 8;
    const __half* Wbase  = Wb + (size_t)(col0 + ldr)  * K + ldc * 8;
    const __half* Wbase1 = Wb + (size_t)(col0 + ldr1) * K + ldc * 8;
    const int okA0 = (row0 + ldr)  < M ? 16 : 0;
    const int okA1 = (row0 + ldr1) < M ? 16 : 0;

    auto load_tile = [&](int kt, int st) {
        uint32_t sa = sbase + st * 2 * TILE_B;
        uint32_t sb = sa + TILE_B;
        cp_async16(sa + ldoff0, Abase  + kt * BK, okA0);
        cp_async16(sa + ldoff1, Abase1 + kt * BK, okA1);
        cp_async16(sb + ldoff0, Wbase  + kt * BK, 16);
        cp_async16(sb + ldoff1, Wbase1 + kt * BK, 16);
        asm volatile("cp.async.commit_group;");
    };

    uint32_t aoff[2][4], boff[2][2];
    #pragma unroll
    for (int ks = 0; ks < 2; ks++) {
        #pragma unroll
        for (int mf = 0; mf < 4; mf++) {
            int r = wm * 64 + mf * 16 + (lane & 15);
            int c = 2 * ks + (lane >> 4);
            aoff[ks][mf] = (uint32_t)(r * 64 + ((c ^ ((r >> 1) & 3)) << 4));
        }
        #pragma unroll
        for (int nfp = 0; nfp < 2; nfp++) {
            int r = wn * 32 + nfp * 16 + (lane & 7) + ((lane >> 4) & 1) * 8;
            int c = 2 * ks + ((lane >> 3) & 1);
            boff[ks][nfp] = (uint32_t)(r * 64 + ((c ^ ((r >> 1) & 3)) << 4));
        }
    }

    load_tile(0, 0);
    load_tile(1, 1);

    #pragma unroll
    for (int kt = 0; kt < nkt; kt++) {
        if (kt < nkt - 1) asm volatile("cp.async.wait_group 1;");
        else              asm volatile("cp.async.wait_group 0;");
        __syncthreads();
        if (kt + 2 < nkt) load_tile(kt + 2, (kt + 2) % STAGES);

        uint32_t sa = sbase + (kt % STAGES) * 2 * TILE_B;
        uint32_t sb = sa + TILE_B;
        #pragma unroll
        for (int ks = 0; ks < 2; ks++) {
            uint32_t aF[4][4], bF[2][4];
            #pragma unroll
            for (int mf = 0; mf < 4; mf++) ldsm_x4(aF[mf], sa + aoff[ks][mf]);
            #pragma unroll
            for (int nfp = 0; nfp < 2; nfp++) ldsm_x4(bF[nfp], sb + boff[ks][nfp]);
            #pragma unroll
            for (int mf = 0; mf < 4; mf++)
                #pragma unroll
                for (int nf = 0; nf < 4; nf++)
                    mma_f16h(accH[mf][nf], aF[mf],
                             bF[nf >> 1][(nf & 1) * 2], bF[nf >> 1][(nf & 1) * 2 + 1]);
        }
    }

    auto scatter_of = [](int r) -> size_t {
        int bw = r / 49, tok = r - bw * 49;
        int bb = bw / 49, wi = bw - bb * 49;
        int R  = (wi / 7) * 7 + tok / 7;
        int Cl = (wi % 7) * 7 + tok % 7;
        int rr = R + 3;  if (rr >= 49) rr -= 49;
        int cc = Cl + 3; if (cc >= 49) cc -= 49;
        return ((size_t)bb * 2401 + rr * 49 + cc) * 128;
    };

    if (EPI == 1) {
        #pragma unroll
        for (int mf = 0; mf < 4; mf++) {
            #pragma unroll
            for (int hh = 0; hh < 2; hh++) {
                int rl = wm * 64 + mf * 16 + g + hh * 8;
                int r = row0 + rl;
                bool ok = r < M;
                size_t dest = scatter_of(ok ? r : (M - 1));
                float s = 0.f, s2 = 0.f;
                #pragma unroll
                for (int nf = 0; nf < 4; nf++) {
                    int n = wn * 32 + nf * 8 + tg * 2;
                    __half2 hv = *reinterpret_cast<__half2*>(&accH[mf][nf][hh]);
                    float2 a2 = *reinterpret_cast<const float2*>(aux + dest + n);
                    float2 b2 = *reinterpret_cast<const float2*>(bias + n);
                    float2 v;
                    v.x = __low2float(hv)  + b2.x + a2.x;
                    v.y = __high2float(hv) + b2.y + a2.y;
                    if (ok) *reinterpret_cast<float2*>(g_x2 + dest + n) = v;
                    s  += v.x + v.y;
                    s2 += v.x * v.x + v.y * v.y;
                }
                s  += __shfl_xor_sync(0xffffffffu, s,  1);
                s2 += __shfl_xor_sync(0xffffffffu, s2, 1);
                s  += __shfl_xor_sync(0xffffffffu, s,  2);
                s2 += __shfl_xor_sync(0xffffffffu, s2, 2);
                if (tg == 0) {
                    sred[(rl * 4 + wn) * 2]     = s;
                    sred[(rl * 4 + wn) * 2 + 1] = s2;
                }
            }
        }
        __syncthreads();
        #pragma unroll
        for (int mf = 0; mf < 4; mf++) {
            #pragma unroll
            for (int hh = 0; hh < 2; hh++) {
                int rl = wm * 64 + mf * 16 + g + hh * 8;
                int r = row0 + rl;
                bool ok = r < M;
                size_t dest = scatter_of(ok ? r : (M - 1));
                float ts = 0.f, ts2 = 0.f;
                #pragma unroll
                for (int q = 0; q < 4; q++) {
                    ts  += sred[(rl * 4 + q) * 2];
                    ts2 += sred[(rl * 4 + q) * 2 + 1];
                }
                float mean = ts * (1.f / 128.f);
                float var  = ts2 * (1.f / 128.f) - mean * mean;
                float rstd = rsqrtf(var + 1e-5f);
                if (ok) {
                    #pragma unroll
                    for (int nf = 0; nf < 4; nf++) {
                        int n = wn * 32 + nf * 8 + tg * 2;
                        float2 v = *reinterpret_cast<const float2*>(g_x2 + dest + n);
                        float2 w2 = *reinterpret_cast<const float2*>(n2w + n);
                        float2 c2 = *reinterpret_cast<const float2*>(n2b + n);
                        __half2 o;
                        o.x = __float2half_rn((v.x - mean) * rstd * w2.x + c2.x);
                        o.y = __float2half_rn((v.y - mean) * rstd * w2.y + c2.y);
                        *reinterpret_cast<uint32_t*>(g_ln2 + dest + n) = *(uint32_t*)&o;
                    }
                }
            }
        }
    } else {
        #pragma unroll
        for (int mf = 0; mf < 4; mf++) {
            #pragma unroll
            for (int hh = 0; hh < 2; hh++) {
                int r = row0 + wm * 64 + mf * 16 + g + hh * 8;
                if (r >= M) continue;
                #pragma unroll
                for (int nf = 0; nf < 4; nf++) {
                    int n = col0 + wn * 32 + nf * 8 + tg * 2;
                    __half2 hv = *reinterpret_cast<__half2*>(&accH[mf][nf][hh]);
                    float2 b2 = *reinterpret_cast<const float2*>(bias + n);
                    float vx = __low2float(hv)  + b2.x;
                    float vy = __high2float(hv) + b2.y;
                    if (EPI == 0) {
                        __half2 o; o.x = __float2half_rn(vx); o.y = __float2half_rn(vy);
                        *reinterpret_cast<uint32_t*>(g_big + (size_t)r * 384 + n) = *(uint32_t*)&o;
                    } else if (EPI == 2) {
                        vx = 0.5f * vx * (1.f + erff(vx * 0.70710678118654752f));
                        vy = 0.5f * vy * (1.f + erff(vy * 0.70710678118654752f));
                        __half2 o; o.x = __float2half_rn(vx); o.y = __float2half_rn(vy);
                        *reinterpret_cast<uint32_t*>(g_big + (size_t)r * 512 + n) = *(uint32_t*)&o;
                    } else {
                        float2 x2v = *reinterpret_cast<const float2*>(g_x2 + (size_t)r * 128 + n);
                        float2 o; o.x = vx + x2v.x; o.y = vy + x2v.y;
                        *reinterpret_cast<float2*>(extC + (size_t)r * 128 + n) = o;
                    }
                }
            }
        }
    }
}

// ---------------- launch ----------------
extern "C" void kernel_launch(void* const* d_in, const int* in_sizes, int n_in,
                              void* d_out, int out_size) {
    const float* x      = (const float*)d_in[0];
    const float* n1w    = (const float*)d_in[1];
    const float* n1b    = (const float*)d_in[2];
    const float* qkv_w  = (const float*)d_in[3];
    const float* qkv_b  = (const float*)d_in[4];
    const float* proj_w = (const float*)d_in[5];
    const float* proj_b = (const float*)d_in[6];
    const float* rpb    = (const float*)d_in[7];
    const float* n2w    = (const float*)d_in[8];
    const float* n2b    = (const float*)d_in[9];
    const float* fc1_w  = (const float*)d_in[10];
    const float* fc1_b  = (const float*)d_in[11];
    const float* fc2_w  = (const float*)d_in[12];
    const float* fc2_b  = (const float*)d_in[13];
    float* out = (float*)d_out;

    const int M = MROWS;
    const int gm = (M + 127) / 128;   // 901

    cvt_weights<<<256, 256>>>(qkv_w, proj_w, fc1_w, fc2_w, qkv_b);
    build_bm<<<dim3(49, 4), 256>>>(rpb);
    ln1_gather_kernel<<<(M + 7) / 8, 256>>>(x, n1w, n1b);

    __half* wbase;
    float* qb;
    cudaGetSymbolAddress((void**)&wbase, g_wts);
    cudaGetSymbolAddress((void**)&qb, g_qkvb);

    mma_gemm<0, 128><<<dim3(gm, 3), 256>>>(wbase + WOFF_QKV, qb, nullptr, nullptr, nullptr, nullptr, M);
    attn_kernel<<<dim3(BN * NWIN, 4), 128>>>();
    mma_gemm<1, 128><<<dim3(gm, 1), 256>>>(wbase + WOFF_PROJ, proj_b, x, nullptr, n2w, n2b, M);
    mma_gemm<2, 128><<<dim3(gm, 4), 256>>>(wbase + WOFF_FC1, fc1_b, nullptr, nullptr, nullptr, nullptr, M);
    mma_gemm<3, 512><<<dim3(gm, 1), 256>>>(wbase + WOFF_FC2, fc2_b, nullptr, out, nullptr, nullptr, M);
}